// round 4
// baseline (speedup 1.0000x reference)
#include <cuda_runtime.h>

#define TLEN 65536
#define INPD 5
#define HD 100
#define HP 104            // padded h length: 26 float4 chunks
#define G4 400            // 4*HD
#define THR 800           // fused kernel block size (split-K x2)
#define CHUNK 4
#define NCHUNK (TLEN / CHUNK)
#define XG_TILE 16

// ---------------- static device scratch ----------------
__device__ float g_xg0[(size_t)TLEN * G4];
__device__ float g_xg1[(size_t)TLEN * G4];
__device__ float g_h1[(size_t)TLEN * HD];
__device__ float g_h2[(size_t)TLEN * HD];
__device__ int   g_prog0;           // layer-0 chunks completed
__device__ int   g_ready[NCHUNK];   // xg1 chunk ready flags

// ---------------- helpers ----------------
typedef unsigned long long u64;

__device__ __forceinline__ u64 ffma2(u64 a, u64 b, u64 c) {
    u64 d;
    asm("fma.rn.f32x2 %0, %1, %2, %3;" : "=l"(d) : "l"(a), "l"(b), "l"(c));
    return d;
}
#define ONE2 0x3F8000003F800000ull
__device__ __forceinline__ u64 fadd2(u64 a, u64 b) { return ffma2(a, ONE2, b); }
__device__ __forceinline__ float2 unpack2(u64 v) {
    float2 r;
    asm("mov.b64 {%0, %1}, %2;" : "=f"(r.x), "=f"(r.y) : "l"(v));
    return r;
}
__device__ __forceinline__ float tanh_ap(float x) {
    float y;
    asm("tanh.approx.f32 %0, %1;" : "=f"(y) : "f"(x));
    return y;
}
__device__ __forceinline__ float sigmoid_ap(float x) {
    return __fmaf_rn(0.5f, tanh_ap(0.5f * x), 0.5f);
}

// load 13 float4 weight chunks for this thread's half (half1 chunk 12 = zeros)
__device__ __forceinline__ void load_whalf(u64* w, const float* rowp, int half) {
    const ulonglong2* wr = (const ulonglong2*)rowp + (half ? 13 : 0);
#pragma unroll
    for (int k = 0; k < 13; k++) {
        ulonglong2 v;
        if (!half || k < 12) v = wr[k];
        else { v.x = 0ull; v.y = 0ull; }
        w[2 * k] = v.x;
        w[2 * k + 1] = v.y;
    }
}

// 52-element half-dot: 13 float4 chunks from (16B-aligned) padded smem vector
__device__ __forceinline__ float dot_half(const u64* __restrict__ w,
                                          const float* __restrict__ hvec, int base) {
    const ulonglong2* hp = (const ulonglong2*)hvec + base;
    u64 a0 = 0ull, a1 = 0ull, a2 = 0ull, a3 = 0ull;
#pragma unroll
    for (int k = 0; k < 13; k++) {
        ulonglong2 hv = hp[k];
        if (k & 1) {
            a2 = ffma2(w[2 * k], hv.x, a2);
            a3 = ffma2(w[2 * k + 1], hv.y, a3);
        } else {
            a0 = ffma2(w[2 * k], hv.x, a0);
            a1 = ffma2(w[2 * k + 1], hv.y, a1);
        }
    }
    a0 = fadd2(a0, a1);
    a2 = fadd2(a2, a3);
    a0 = fadd2(a0, a2);
    float2 s = unpack2(a0);
    return s.x + s.y;
}

// ---------------- phase 1: xg0 = Wih0 @ x[t] + bih0 + bhh0 (+ flag reset) ------
__global__ void xg0_kernel(const float* __restrict__ x,
                           const float* __restrict__ Wih0,
                           const float* __restrict__ bih0,
                           const float* __restrict__ bhh0) {
    int g = threadIdx.x;                 // 0..399
    if (blockIdx.x == 0) {               // reset cross-block flags for this run
        for (int i = g; i < NCHUNK; i += G4) g_ready[i] = 0;
        if (g == 0) g_prog0 = 0;
    }
    int t0 = blockIdx.x * XG_TILE;
    float w0 = __ldg(Wih0 + g * INPD + 0);
    float w1 = __ldg(Wih0 + g * INPD + 1);
    float w2 = __ldg(Wih0 + g * INPD + 2);
    float w3 = __ldg(Wih0 + g * INPD + 3);
    float w4 = __ldg(Wih0 + g * INPD + 4);
    float b = __ldg(bih0 + g) + __ldg(bhh0 + g);
#pragma unroll
    for (int tt = 0; tt < XG_TILE; tt++) {
        const float* xr = x + (size_t)(t0 + tt) * INPD;
        float acc = b;
        acc = __fmaf_rn(w0, __ldg(xr + 0), acc);
        acc = __fmaf_rn(w1, __ldg(xr + 1), acc);
        acc = __fmaf_rn(w2, __ldg(xr + 2), acc);
        acc = __fmaf_rn(w3, __ldg(xr + 3), acc);
        acc = __fmaf_rn(w4, __ldg(xr + 4), acc);
        g_xg0[(size_t)(t0 + tt) * G4 + g] = acc;
    }
}

// ---------------- recurrence body (one block, 800 threads, split-K x2) --------
// tid = 8*j + 2*q + half : unit j (0..99), gate q (0:i 1:f 2:g 3:o), k-half
template <bool RELEASE, bool WAIT>
__device__ void rec_body(const float* __restrict__ Whh,
                         const float* __restrict__ xg,
                         float* __restrict__ hout,
                         float* __restrict__ h_s /* [2][HP] smem, 16B aligned */) {
    int tid = threadIdx.x;
    int j = tid >> 3;
    int r = tid & 7;
    int q = r >> 1;
    int half = r & 1;
    int row = q * HD + j;
    int base = half ? 13 : 0;

    u64 w[26];
    load_whalf(w, Whh + (size_t)row * HD, half);

    if (tid < 2 * HP) h_s[tid] = 0.f;    // includes pads
    float c = 0.f;

    if (WAIT) {
        while (((volatile int*)g_ready)[0] == 0) __nanosleep(40);
        __threadfence();
    }
    float xr[CHUNK];
    {
        const float* xp = xg + row;
#pragma unroll
        for (int s = 0; s < CHUNK; s++) xr[s] = __ldcg(xp + (size_t)s * G4);
    }
    __syncthreads();

    int t = 0;
#pragma unroll 1
    for (int c0 = 0; c0 < NCHUNK; c0++) {
        float xc[CHUNK];
#pragma unroll
        for (int s = 0; s < CHUNK; s++) xc[s] = xr[s];

        if (c0 + 1 < NCHUNK) {           // prefetch next chunk, off critical path
            if (WAIT) {
                while (((volatile int*)g_ready)[c0 + 1] == 0) __nanosleep(40);
                __threadfence();
            }
            const float* xp = xg + (size_t)(c0 + 1) * CHUNK * G4 + row;
#pragma unroll
            for (int s = 0; s < CHUNK; s++) xr[s] = __ldcg(xp + (size_t)s * G4);
        }

#pragma unroll 1
        for (int s = 0; s < CHUNK; s++, t++) {
            float p = dot_half(w, h_s + (t & 1) * HP, base);
            if (!half) p += xc[s];
            p += __shfl_xor_sync(0xffffffffu, p, 1);           // combine halves
            float act = (q == 2) ? tanh_ap(p) : sigmoid_ap(p);
            float fv = __shfl_down_sync(0xffffffffu, act, 2, 8);
            float gg = __shfl_down_sync(0xffffffffu, act, 4, 8);
            float ov = __shfl_down_sync(0xffffffffu, act, 6, 8);
            if (r == 0) {
                c = __fmaf_rn(fv, c, act * gg);
                float h = ov * tanh_ap(c);
                h_s[((t + 1) & 1) * HP + j] = h;
                __stcg(hout + (size_t)t * HD + j, h);
            }
            __syncthreads();
        }

        if (RELEASE && tid == 0) {
            __threadfence();
            *((volatile int*)&g_prog0) = c0 + 1;
        }
    }
}

// ---------------- xg1 streaming body (2 blocks, alternate chunks) -------------
// tid = 2*row + half : 400 rows, split-K x2
__device__ void xg_body(const float* __restrict__ Wih1,
                        const float* __restrict__ bih1,
                        const float* __restrict__ bhh1, int b,
                        float* __restrict__ hbuf /* [CHUNK][HP] smem */) {
    int tid = threadIdx.x;
    int row = tid >> 1;
    int half = tid & 1;
    int base = half ? 13 : 0;

    u64 w[26];
    load_whalf(w, Wih1 + (size_t)row * HD, half);
    float bb = __ldg(bih1 + row) + __ldg(bhh1 + row);

    if (tid < CHUNK * 4) {               // zero pad slots once
        int s = tid >> 2, p = tid & 3;
        hbuf[s * HP + HD + p] = 0.f;
    }

#pragma unroll 1
    for (int c0 = b; c0 < NCHUNK; c0 += 2) {
        while (*((volatile int*)&g_prog0) < c0 + 1) __nanosleep(40);
        __threadfence();
        __syncthreads();                 // protect hbuf reuse
        for (int i = tid; i < CHUNK * HD; i += THR)
            hbuf[(i / HD) * HP + (i % HD)] = __ldcg(g_h1 + (size_t)c0 * CHUNK * HD + i);
        __syncthreads();

#pragma unroll 1
        for (int s = 0; s < CHUNK; s++) {
            float p = dot_half(w, hbuf + s * HP, base);
            p += __shfl_xor_sync(0xffffffffu, p, 1);
            if (!half)
                __stcg(g_xg1 + (size_t)(c0 * CHUNK + s) * G4 + row, p + bb);
        }
        __syncthreads();
        if (tid == 0) {
            __threadfence();
            *((volatile int*)&g_ready[c0]) = 1;
        }
    }
}

// ---------------- fused pipelined kernel: grid = 4 blocks ----------------
__global__ __launch_bounds__(THR, 1)
void fused_kernel(const float* __restrict__ Whh0,
                  const float* __restrict__ Whh1,
                  const float* __restrict__ Wih1,
                  const float* __restrict__ bih1,
                  const float* __restrict__ bhh1) {
    __shared__ __align__(16) float smem_pool[CHUNK * HP];   // 1664 B
    int b = blockIdx.x;
    if (b == 0)
        rec_body<true, false>(Whh0, g_xg0, g_h1, smem_pool);
    else if (b <= 2)
        xg_body(Wih1, bih1, bhh1, b - 1, smem_pool);
    else
        rec_body<false, true>(Whh1, g_xg1, g_h2, smem_pool);
}

// ---------------- final linear + sigmoid ----------------
__global__ void out_kernel(const float* __restrict__ Wlin,
                           const float* __restrict__ blin,
                           float* __restrict__ out) {
    int warp = (blockIdx.x * blockDim.x + threadIdx.x) >> 5;
    int lane = threadIdx.x & 31;
    if (warp >= TLEN) return;
    const float* hr = g_h2 + (size_t)warp * HD;
    float acc = 0.f;
#pragma unroll
    for (int k = 0; k < 4; k++) {
        int idx = lane + 32 * k;
        if (idx < HD) acc = __fmaf_rn(hr[idx], __ldg(Wlin + idx), acc);
    }
#pragma unroll
    for (int o = 16; o; o >>= 1) acc += __shfl_down_sync(0xffffffffu, acc, o);
    if (lane == 0) out[warp] = sigmoid_ap(acc + __ldg(blin));
}

// ---------------- launch ----------------
extern "C" void kernel_launch(void* const* d_in, const int* in_sizes, int n_in,
                              void* d_out, int out_size) {
    const float* x    = (const float*)d_in[0];
    const float* Wih0 = (const float*)d_in[1];
    const float* Whh0 = (const float*)d_in[2];
    const float* bih0 = (const float*)d_in[3];
    const float* bhh0 = (const float*)d_in[4];
    const float* Wih1 = (const float*)d_in[5];
    const float* Whh1 = (const float*)d_in[6];
    const float* bih1 = (const float*)d_in[7];
    const float* bhh1 = (const float*)d_in[8];
    const float* Wlin = (const float*)d_in[9];
    const float* blin = (const float*)d_in[10];
    float* out = (float*)d_out;

    xg0_kernel<<<TLEN / XG_TILE, G4>>>(x, Wih0, bih0, bhh0);
    fused_kernel<<<4, THR>>>(Whh0, Whh1, Wih1, bih1, bhh1);
    out_kernel<<<(TLEN * 32) / 256, 256>>>(Wlin, blin, out);
}

// round 5
// speedup vs baseline: 1.5757x; 1.5757x over previous
#include <cuda_runtime.h>

#define TLEN 65536
#define INPD 5
#define HD 100
#define HP 104            // padded h length (16B-aligned chunks)
#define G4 400            // 4*HD
#define CHUNK 8
#define NCHUNK (TLEN / CHUNK)
#define XG_TILE 16

// ---------------- static device scratch ----------------
__device__ float g_xg0[(size_t)TLEN * G4];
__device__ float g_xg1[(size_t)TLEN * G4];
__device__ float g_h1[(size_t)TLEN * HD];
__device__ float g_h2[(size_t)TLEN * HD];
__device__ int   g_prog0;           // layer-0 chunks completed
__device__ int   g_ready[NCHUNK];   // xg1 chunk ready flags

// ---------------- helpers ----------------
typedef unsigned long long u64;

__device__ __forceinline__ u64 ffma2(u64 a, u64 b, u64 c) {
    u64 d;
    asm("fma.rn.f32x2 %0, %1, %2, %3;" : "=l"(d) : "l"(a), "l"(b), "l"(c));
    return d;
}
#define ONE2 0x3F8000003F800000ull
__device__ __forceinline__ u64 fadd2(u64 a, u64 b) { return ffma2(a, ONE2, b); }
__device__ __forceinline__ float2 unpack2(u64 v) {
    float2 r;
    asm("mov.b64 {%0, %1}, %2;" : "=f"(r.x), "=f"(r.y) : "l"(v));
    return r;
}
__device__ __forceinline__ u64 pack2(float lo, float hi) {
    u64 v;
    asm("mov.b64 %0, {%1, %2};" : "=l"(v) : "f"(lo), "f"(hi));
    return v;
}
__device__ __forceinline__ float tanh_ap(float x) {
    float y;
    asm("tanh.approx.f32 %0, %1;" : "=f"(y) : "f"(x));
    return y;
}
__device__ __forceinline__ float sigmoid_ap(float x) {
    return __fmaf_rn(0.5f, tanh_ap(0.5f * x), 0.5f);
}
__device__ __forceinline__ int ld_acq(const int* p) {
    int v;
    asm volatile("ld.acquire.gpu.global.b32 %0, [%1];" : "=r"(v) : "l"(p) : "memory");
    return v;
}

// 100-dot against register weights w[50] (f32x2), smem h vector, init value
__device__ __forceinline__ float dot100x(const u64* __restrict__ w,
                                         const float* __restrict__ hvec, float init) {
    const ulonglong2* hp = (const ulonglong2*)hvec;
    u64 a0 = pack2(init, 0.f);
    u64 a1 = 0ull, a2 = 0ull, a3 = 0ull;
#pragma unroll
    for (int k = 0; k < HD / 4; k++) {
        ulonglong2 hv = hp[k];
        if (k & 1) {
            a2 = ffma2(w[2 * k], hv.x, a2);
            a3 = ffma2(w[2 * k + 1], hv.y, a3);
        } else {
            a0 = ffma2(w[2 * k], hv.x, a0);
            a1 = ffma2(w[2 * k + 1], hv.y, a1);
        }
    }
    a0 = fadd2(a0, a1);
    a2 = fadd2(a2, a3);
    a0 = fadd2(a0, a2);
    float2 s = unpack2(a0);
    return s.x + s.y;
}

__device__ __forceinline__ void load_wrow(u64* w, const float* row) {
    const ulonglong2* wr = (const ulonglong2*)row;
#pragma unroll
    for (int k = 0; k < HD / 4; k++) {
        ulonglong2 v = wr[k];
        w[2 * k] = v.x;
        w[2 * k + 1] = v.y;
    }
}

// ---------------- phase 1: xg0 = Wih0 @ x[t] + bih0 + bhh0 (+ flag reset) ------
__global__ void xg0_kernel(const float* __restrict__ x,
                           const float* __restrict__ Wih0,
                           const float* __restrict__ bih0,
                           const float* __restrict__ bhh0) {
    int g = threadIdx.x;                 // 0..399
    if (blockIdx.x == 0) {               // reset cross-block flags for this run
        for (int i = g; i < NCHUNK; i += G4) g_ready[i] = 0;
        if (g == 0) g_prog0 = 0;
    }
    int t0 = blockIdx.x * XG_TILE;
    float w0 = __ldg(Wih0 + g * INPD + 0);
    float w1 = __ldg(Wih0 + g * INPD + 1);
    float w2 = __ldg(Wih0 + g * INPD + 2);
    float w3 = __ldg(Wih0 + g * INPD + 3);
    float w4 = __ldg(Wih0 + g * INPD + 4);
    float b = __ldg(bih0 + g) + __ldg(bhh0 + g);
#pragma unroll
    for (int tt = 0; tt < XG_TILE; tt++) {
        const float* xr = x + (size_t)(t0 + tt) * INPD;
        float acc = b;
        acc = __fmaf_rn(w0, __ldg(xr + 0), acc);
        acc = __fmaf_rn(w1, __ldg(xr + 1), acc);
        acc = __fmaf_rn(w2, __ldg(xr + 2), acc);
        acc = __fmaf_rn(w3, __ldg(xr + 3), acc);
        acc = __fmaf_rn(w4, __ldg(xr + 4), acc);
        g_xg0[(size_t)(t0 + tt) * G4 + g] = acc;
    }
}

// ---------------- recurrence body (one block, 400 threads) ----------------
// tid = 4*j + q : unit j (0..99), gate q (0:i 1:f 2:g 3:o); row = q*HD + j
template <bool RELEASE, bool WAIT>
__device__ void rec_body(const float* __restrict__ Whh,
                         const float* __restrict__ xg,
                         float* __restrict__ hout,
                         float* __restrict__ h_s /* [2][HP] smem */) {
    int tid = threadIdx.x;
    int j = tid >> 2, q = tid & 3;
    int row = q * HD + j;
    unsigned mask = __activemask();

    u64 w[HD / 2];
    load_wrow(w, Whh + (size_t)row * HD);

    if (tid < 2 * HP) h_s[tid] = 0.f;
    float c = 0.f;

    if (WAIT) {
        while (ld_acq(&g_ready[0]) == 0) __nanosleep(40);
    }
    float xr[CHUNK];
    {
        const float* xp = xg + row;
#pragma unroll
        for (int s = 0; s < CHUNK; s++) xr[s] = __ldcg(xp + (size_t)s * G4);
    }
    __syncthreads();

#pragma unroll 1
    for (int c0 = 0; c0 < NCHUNK; c0++) {
        float xc[CHUNK];
#pragma unroll
        for (int s = 0; s < CHUNK; s++) xc[s] = xr[s];

        if (c0 + 1 < NCHUNK) {           // prefetch next chunk, off critical path
            if (WAIT) {
                while (ld_acq(&g_ready[c0 + 1]) == 0) __nanosleep(40);
            }
            const float* xp = xg + (size_t)(c0 + 1) * CHUNK * G4 + row;
#pragma unroll
            for (int s = 0; s < CHUNK; s++) xr[s] = __ldcg(xp + (size_t)s * G4);
        }

#pragma unroll
        for (int s = 0; s < CHUNK; s++) {              // fully unrolled: static smem offsets
            float gv = dot100x(w, h_s + (s & 1) * HP, xc[s]);
            float act = (q == 2) ? tanh_ap(gv) : sigmoid_ap(gv);
            float fv = __shfl_down_sync(mask, act, 1, 4);
            float gg = __shfl_down_sync(mask, act, 2, 4);
            float ov = __shfl_down_sync(mask, act, 3, 4);
            if (q == 0) {
                c = __fmaf_rn(fv, c, act * gg);
                float h = ov * tanh_ap(c);
                h_s[((s + 1) & 1) * HP + j] = h;
                __stcg(hout + (size_t)(c0 * CHUNK + s) * HD + j, h);
            }
            __syncthreads();
        }

        if (RELEASE && tid == 0) {
            __threadfence();
            *((volatile int*)&g_prog0) = c0 + 1;
        }
    }
}

// ---------------- xg1 streaming body (2 blocks, alternate chunks) -------------
__device__ void xg_body(const float* __restrict__ Wih1,
                        const float* __restrict__ bih1,
                        const float* __restrict__ bhh1, int b,
                        float* __restrict__ hbuf /* [CHUNK][HP] smem */) {
    int tid = threadIdx.x;               // 0..399 = gate row

    u64 w[HD / 2];
    load_wrow(w, Wih1 + (size_t)tid * HD);
    float bb = __ldg(bih1 + tid) + __ldg(bhh1 + tid);

    if (tid < CHUNK * 4) {               // zero the pad slots once
        int s = tid >> 2, p = tid & 3;
        hbuf[s * HP + HD + p] = 0.f;
    }

#pragma unroll 1
    for (int c0 = b; c0 < NCHUNK; c0 += 2) {
        while (ld_acq(&g_prog0) < c0 + 1) __nanosleep(40);
        __syncthreads();                 // protect hbuf reuse
        for (int i = tid; i < CHUNK * HD; i += G4)
            hbuf[(i / HD) * HP + (i % HD)] = __ldcg(g_h1 + (size_t)c0 * CHUNK * HD + i);
        __syncthreads();

#pragma unroll
        for (int s = 0; s < CHUNK; s++) {
            float v = dot100x(w, hbuf + s * HP, bb);
            __stcg(g_xg1 + (size_t)(c0 * CHUNK + s) * G4 + tid, v);
        }
        __syncthreads();
        if (tid == 0) {
            __threadfence();
            *((volatile int*)&g_ready[c0]) = 1;
        }
    }
}

// ---------------- fused pipelined kernel: grid = 4 blocks ----------------
__global__ __launch_bounds__(G4, 1)
void fused_kernel(const float* __restrict__ Whh0,
                  const float* __restrict__ Whh1,
                  const float* __restrict__ Wih1,
                  const float* __restrict__ bih1,
                  const float* __restrict__ bhh1) {
    __shared__ __align__(16) float smem_pool[CHUNK * HP];   // 3328 B
    int b = blockIdx.x;
    if (b == 0)
        rec_body<true, false>(Whh0, g_xg0, g_h1, smem_pool);
    else if (b <= 2)
        xg_body(Wih1, bih1, bhh1, b - 1, smem_pool);
    else
        rec_body<false, true>(Whh1, g_xg1, g_h2, smem_pool);
}

// ---------------- final linear + sigmoid ----------------
__global__ void out_kernel(const float* __restrict__ Wlin,
                           const float* __restrict__ blin,
                           float* __restrict__ out) {
    int warp = (blockIdx.x * blockDim.x + threadIdx.x) >> 5;
    int lane = threadIdx.x & 31;
    if (warp >= TLEN) return;
    const float* hr = g_h2 + (size_t)warp * HD;
    float acc = 0.f;
#pragma unroll
    for (int k = 0; k < 4; k++) {
        int idx = lane + 32 * k;
        if (idx < HD) acc = __fmaf_rn(hr[idx], __ldg(Wlin + idx), acc);
    }
#pragma unroll
    for (int o = 16; o; o >>= 1) acc += __shfl_down_sync(0xffffffffu, acc, o);
    if (lane == 0) out[warp] = sigmoid_ap(acc + __ldg(blin));
}

// ---------------- launch ----------------
extern "C" void kernel_launch(void* const* d_in, const int* in_sizes, int n_in,
                              void* d_out, int out_size) {
    const float* x    = (const float*)d_in[0];
    const float* Wih0 = (const float*)d_in[1];
    const float* Whh0 = (const float*)d_in[2];
    const float* bih0 = (const float*)d_in[3];
    const float* bhh0 = (const float*)d_in[4];
    const float* Wih1 = (const float*)d_in[5];
    const float* Whh1 = (const float*)d_in[6];
    const float* bih1 = (const float*)d_in[7];
    const float* bhh1 = (const float*)d_in[8];
    const float* Wlin = (const float*)d_in[9];
    const float* blin = (const float*)d_in[10];
    float* out = (float*)d_out;

    xg0_kernel<<<TLEN / XG_TILE, G4>>>(x, Wih0, bih0, bhh0);
    fused_kernel<<<4, G4>>>(Whh0, Whh1, Wih1, bih1, bhh1);
    out_kernel<<<(TLEN * 32) / 256, 256>>>(Wlin, blin, out);
}